// round 10
// baseline (speedup 1.0000x reference)
#include <cuda_runtime.h>
#include <cstdint>

#define N_NODES 50000
#define MAX_EDGES 800000
#define EMB 128
#define NRBF 20

// Scratch (static device arrays are allowed; runtime alloc is not)
__device__ float g_h[(size_t)N_NODES * EMB];         // silu(s@W1+b1)
__device__ float g_spass[(size_t)N_NODES * 3 * EMB]; // h@W2+b2
__device__ int   g_hist[N_NODES];                    // histogram -> offsets (cursor)
__device__ int2  g_sorted_sd[MAX_EDGES];             // (src, dst) sorted by dst
__device__ int   g_sorted_idx[MAX_EDGES];            // original edge index

// ---------- tf32 mma helpers ----------
__device__ __forceinline__ unsigned tf32_of(float f) {
    unsigned r;
    asm("cvt.rna.tf32.f32 %0, %1;" : "=r"(r) : "f"(f));
    return r;
}
__device__ __forceinline__ void mma_tf32(float c[4],
                                         unsigned a0, unsigned a1,
                                         unsigned a2, unsigned a3,
                                         unsigned b0, unsigned b1) {
    asm("mma.sync.aligned.m16n8k8.row.col.f32.tf32.tf32.f32 "
        "{%0,%1,%2,%3}, {%4,%5,%6,%7}, {%8,%9}, {%0,%1,%2,%3};"
        : "+f"(c[0]), "+f"(c[1]), "+f"(c[2]), "+f"(c[3])
        : "r"(a0), "r"(a1), "r"(a2), "r"(a3), "r"(b0), "r"(b1));
}

// ---------- tensor-core GEMM: C[M x N] = act(A[M x 128] @ W[128 x N] + b) ----------
#define A_STRIDE 132
#define W_STRIDE 72
#define TG_SMEM_BYTES ((128 * A_STRIDE + 32 * W_STRIDE) * 4)

template <int N, int ACT>
__device__ __forceinline__ void gemm_tc_body(
    const float* __restrict__ A, const float* __restrict__ W,
    const float* __restrict__ bias, float* __restrict__ C, int M)
{
    extern __shared__ __align__(16) unsigned smem_u[];
    unsigned* A_sh = smem_u;                    // [128][A_STRIDE]
    unsigned* W_sh = smem_u + 128 * A_STRIDE;   // [32][W_STRIDE]

    const int t = threadIdx.x;
    const int w = t >> 5;
    const int lane = t & 31;
    const int mw = w & 3;
    const int nw = w >> 2;
    const int lr = lane >> 2;
    const int lc = lane & 3;
    const int m0 = blockIdx.x * 128;

    for (int lin = t; lin < 128 * 128; lin += 256) {
        int m = lin >> 7, k = lin & 127;
        float val = (m0 + m < M) ? A[(size_t)(m0 + m) * 128 + k] : 0.f;
        A_sh[m * A_STRIDE + k] = tf32_of(val);
    }

    for (int n0 = 0; n0 < N; n0 += 64) {
        float acc[2][4][4];
        #pragma unroll
        for (int i = 0; i < 2; i++)
            #pragma unroll
            for (int j = 0; j < 4; j++)
                #pragma unroll
                for (int x = 0; x < 4; x++) acc[i][j][x] = 0.f;

        #pragma unroll 1
        for (int kc = 0; kc < 4; kc++) {
            __syncthreads();
            for (int lin = t; lin < 32 * 64; lin += 256) {
                int kk = lin >> 6, nn = lin & 63;
                W_sh[kk * W_STRIDE + nn] =
                    tf32_of(W[(size_t)(kc * 32 + kk) * N + n0 + nn]);
            }
            __syncthreads();

            #pragma unroll
            for (int k8 = 0; k8 < 4; k8++) {
                const int kl = k8 * 8;
                const int kg = kc * 32 + kl;
                unsigned a[2][4];
                #pragma unroll
                for (int i = 0; i < 2; i++) {
                    const int r = mw * 32 + i * 16 + lr;
                    a[i][0] = A_sh[r * A_STRIDE + kg + lc];
                    a[i][1] = A_sh[(r + 8) * A_STRIDE + kg + lc];
                    a[i][2] = A_sh[r * A_STRIDE + kg + lc + 4];
                    a[i][3] = A_sh[(r + 8) * A_STRIDE + kg + lc + 4];
                }
                #pragma unroll
                for (int j = 0; j < 4; j++) {
                    const int n = nw * 32 + j * 8 + lr;
                    unsigned b0 = W_sh[(kl + lc) * W_STRIDE + n];
                    unsigned b1 = W_sh[(kl + lc + 4) * W_STRIDE + n];
                    mma_tf32(acc[0][j], a[0][0], a[0][1], a[0][2], a[0][3], b0, b1);
                    mma_tf32(acc[1][j], a[1][0], a[1][1], a[1][2], a[1][3], b0, b1);
                }
            }
        }

        #pragma unroll
        for (int i = 0; i < 2; i++) {
            const int r1 = m0 + mw * 32 + i * 16 + lr;
            const int r2 = r1 + 8;
            #pragma unroll
            for (int j = 0; j < 4; j++) {
                const int cb = n0 + nw * 32 + j * 8 + lc * 2;
                const float b0f = bias[cb], b1f = bias[cb + 1];
                float x0 = acc[i][j][0] + b0f;
                float x1 = acc[i][j][1] + b1f;
                float x2 = acc[i][j][2] + b0f;
                float x3 = acc[i][j][3] + b1f;
                if (ACT) {
                    x0 = x0 / (1.0f + __expf(-x0));
                    x1 = x1 / (1.0f + __expf(-x1));
                    x2 = x2 / (1.0f + __expf(-x2));
                    x3 = x3 / (1.0f + __expf(-x3));
                }
                if (r1 < M) *(float2*)(C + (size_t)r1 * N + cb) = make_float2(x0, x1);
                if (r2 < M) *(float2*)(C + (size_t)r2 * N + cb) = make_float2(x2, x3);
            }
        }
    }
}

__global__ __launch_bounds__(256) void gemm1_kernel(
    const float* __restrict__ A, const float* __restrict__ W,
    const float* __restrict__ bias, int M)
{
    gemm_tc_body<128, 1>(A, W, bias, g_h, M);
}

__global__ __launch_bounds__(256) void gemm2_kernel(
    const float* __restrict__ W, const float* __restrict__ bias, int M)
{
    gemm_tc_body<384, 0>(g_h, W, bias, g_spass, M);
}

// ---------- counting sort of edges by dst ----------
__global__ __launch_bounds__(256) void hist_kernel(const int* __restrict__ edges,
                                                   int n_edges)
{
    int e = blockIdx.x * 256 + threadIdx.x;
    if (e < n_edges) atomicAdd(&g_hist[edges[2 * e + 1]], 1);
}

__global__ __launch_bounds__(1024) void scan_kernel()
{
    __shared__ int warp_sums[32];
    __shared__ int running_sh;
    const int t = threadIdx.x;
    const int lane = t & 31, wid = t >> 5;
    if (t == 0) running_sh = 0;
    __syncthreads();

    for (int base = 0; base < N_NODES; base += 1024) {
        int i = base + t;
        int v = (i < N_NODES) ? g_hist[i] : 0;
        int x = v;
        #pragma unroll
        for (int d = 1; d < 32; d <<= 1) {
            int y = __shfl_up_sync(~0u, x, d);
            if (lane >= d) x += y;
        }
        if (lane == 31) warp_sums[wid] = x;
        __syncthreads();
        if (wid == 0) {
            int s2 = warp_sums[lane];
            #pragma unroll
            for (int d = 1; d < 32; d <<= 1) {
                int y = __shfl_up_sync(~0u, s2, d);
                if (lane >= d) s2 += y;
            }
            warp_sums[lane] = s2;
        }
        __syncthreads();
        int incl = x + (wid > 0 ? warp_sums[wid - 1] : 0) + running_sh;
        if (i < N_NODES) g_hist[i] = incl - v;
        __syncthreads();
        if (t == 1023) running_sh = incl;
        __syncthreads();
    }
}

__global__ __launch_bounds__(256) void scatter_kernel(const int* __restrict__ edges,
                                                      int n_edges)
{
    int e = blockIdx.x * 256 + threadIdx.x;
    if (e < n_edges) {
        int2 sd = ((const int2*)edges)[e];
        int pos = atomicAdd(&g_hist[sd.y], 1);
        g_sorted_sd[pos] = sd;
        g_sorted_idx[pos] = e;
    }
}

// ---------- Edge kernel v3: tensor-core rbf@Wr + dst-cached gathers ----------
// 256 threads / 8 warps, 64 edges per block (dst-sorted).
// smem carve (float words): pass[64*132] | rbf[64*28] | wr[24*136] | fc[64]
//                           | rn[64*3] | src[64] | dst[64]
#define EPB 64
#define P_STR 132
#define R_STR 28
#define WR_STR 136
#define PASS_OFF 0
#define RBF_OFF  (EPB * P_STR)                 // 8448
#define WR_OFF   (RBF_OFF + EPB * R_STR)       // 10240
#define FC_OFF   (WR_OFF + 24 * WR_STR)        // 13504
#define RN_OFF   (FC_OFF + EPB)                // 13568
#define SRC_OFF  (RN_OFF + EPB * 3)            // 13760
#define DST_OFF  (SRC_OFF + EPB)               // 13824
#define EDGE_SMEM_WORDS (DST_OFF + EPB)        // 13888
#define EDGE_SMEM_BYTES (EDGE_SMEM_WORDS * 4)

template <int C>
__device__ __forceinline__ void edge_chunk(
    float* smemf, unsigned* smemu,
    const float* __restrict__ Wr, const float* __restrict__ br,
    const float* __restrict__ v_in,
    float* __restrict__ s_out, float* __restrict__ v_out,
    int base, int n_edges, float* dvg_reg)
{
    float* pass_sh = smemf + PASS_OFF;
    unsigned* rbf_sh = smemu + RBF_OFF;
    unsigned* wr_sh = smemu + WR_OFF;
    const float* fc_sh = smemf + FC_OFF;
    const float* rn_sh = smemf + RN_OFF;
    const int* src_sh = (const int*)(smemu + SRC_OFF);
    const int* dst_sh = (const int*)(smemu + DST_OFF);

    const int t = threadIdx.x;
    const int w = t >> 5;
    const int lane = t & 31;
    const int mw = w & 3;        // rows 16*mw..+15
    const int nw = w >> 2;       // cols 64*nw..+63
    const int lr = lane >> 2;
    const int lc = lane & 3;

    // ---- stage Wr chunk (rows 0..19 real, 20..23 zero), cols C*128..+127
    __syncthreads();  // pass_sh free (prev elementwise done), wr_sh free
    for (int lin = t; lin < 24 * 128; lin += 256) {
        int k = lin >> 7, n = lin & 127;
        wr_sh[k * WR_STR + n] =
            (k < NRBF) ? tf32_of(Wr[(size_t)k * 384 + C * 128 + n]) : 0u;
    }
    __syncthreads();

    // ---- MMA: pass[64 x 128] = rbf[64 x 24] @ wr[24 x 128]
    float acc[8][4];
    #pragma unroll
    for (int j = 0; j < 8; j++)
        #pragma unroll
        for (int x = 0; x < 4; x++) acc[j][x] = 0.f;

    #pragma unroll
    for (int kk = 0; kk < 3; kk++) {
        const int kg = kk * 8;
        const int r = 16 * mw + lr;
        unsigned a0 = rbf_sh[r * R_STR + kg + lc];
        unsigned a1 = rbf_sh[(r + 8) * R_STR + kg + lc];
        unsigned a2 = rbf_sh[r * R_STR + kg + lc + 4];
        unsigned a3 = rbf_sh[(r + 8) * R_STR + kg + lc + 4];
        #pragma unroll
        for (int j = 0; j < 8; j++) {
            const int n = 64 * nw + 8 * j + lr;
            unsigned b0 = wr_sh[(kg + lc) * WR_STR + n];
            unsigned b1 = wr_sh[(kg + lc + 4) * WR_STR + n];
            mma_tf32(acc[j], a0, a1, a2, a3, b0, b1);
        }
    }

    // epilogue into pass_sh
    {
        const int r1 = 16 * mw + lr;
        const int r2 = r1 + 8;
        #pragma unroll
        for (int j = 0; j < 8; j++) {
            const int col = 64 * nw + 8 * j + 2 * lc;
            *(float2*)(pass_sh + r1 * P_STR + col) = make_float2(acc[j][0], acc[j][1]);
            *(float2*)(pass_sh + r2 * P_STR + col) = make_float2(acc[j][2], acc[j][3]);
        }
    }
    __syncthreads();

    // ---- elementwise: thread = (col, edge-half)
    const int col = t & 127;
    const int e0 = (t >> 7) * 32;
    const float brv = br[C * 128 + col];

    int dst_prev = -1;
    float spv = 0.f, vv0 = 0.f, vv1 = 0.f, vv2 = 0.f;

    #pragma unroll
    for (int i = 0; i < 32; i++) {
        const int e = e0 + i;
        if (base + e < n_edges) {
            const int dst = dst_sh[e];
            if (dst != dst_prev) {
                spv = g_spass[(size_t)dst * 384 + C * 128 + col];
                if (C == 2) {
                    const float* vp = v_in + (size_t)dst * 384 + col;
                    vv0 = vp[0]; vv1 = vp[128]; vv2 = vp[256];
                }
                dst_prev = dst;
            }
            float val = (pass_sh[e * P_STR + col] + brv) * fc_sh[e] * spv;
            if (C == 0) {
                dvg_reg[i] = val;
            } else if (C == 1) {
                atomicAdd(s_out + (size_t)src_sh[e] * 128 + col, val);
            } else {
                const float d = dvg_reg[i];
                float* vo = v_out + (size_t)src_sh[e] * 384 + col;
                atomicAdd(vo,       fmaf(vv0, d, rn_sh[e * 3 + 0] * val));
                atomicAdd(vo + 128, fmaf(vv1, d, rn_sh[e * 3 + 1] * val));
                atomicAdd(vo + 256, fmaf(vv2, d, rn_sh[e * 3 + 2] * val));
            }
        }
    }
}

__global__ __launch_bounds__(256) void edge_kernel(
    const float* __restrict__ r_ij,        // [E]
    const float* __restrict__ rnorm,       // [E][3]
    const float* __restrict__ Wr,          // [20][384]
    const float* __restrict__ br,          // [384]
    const float* __restrict__ v_in,        // [N][3][128]
    float* __restrict__ s_out,             // [N][128]
    float* __restrict__ v_out,             // [N][3][128]
    int n_edges)
{
    extern __shared__ __align__(16) unsigned smemu[];
    float* smemf = (float*)smemu;

    const int t = threadIdx.x;
    const int base = blockIdx.x * EPB;

    // init: threads 0..63 compute edge data into smem
    if (t < EPB) {
        unsigned* rbf_row = smemu + RBF_OFF + t * R_STR;
        const int e_g = base + t;
        if (e_g < n_edges) {
            int2 sd = g_sorted_sd[e_g];
            int idx = g_sorted_idx[e_g];
            ((int*)(smemu + SRC_OFF))[t] = sd.x;
            ((int*)(smemu + DST_OFF))[t] = sd.y;
            float r = r_ij[idx];
            float inv_r = 1.0f / r;
            float q = r * 0.2f;
            #pragma unroll
            for (int n = 1; n <= NRBF; n++)
                rbf_row[n - 1] = tf32_of(sinpif((float)n * q) * inv_r);
            #pragma unroll
            for (int n = NRBF; n < R_STR; n++) rbf_row[n] = 0u;
            smemf[FC_OFF + t] = (r <= 5.0f) ? 0.5f * (cospif(q) + 1.0f) : 0.0f;
            smemf[RN_OFF + t * 3 + 0] = rnorm[3 * idx + 0];
            smemf[RN_OFF + t * 3 + 1] = rnorm[3 * idx + 1];
            smemf[RN_OFF + t * 3 + 2] = rnorm[3 * idx + 2];
        } else {
            #pragma unroll
            for (int n = 0; n < R_STR; n++) rbf_row[n] = 0u;
            ((int*)(smemu + SRC_OFF))[t] = 0;
            ((int*)(smemu + DST_OFF))[t] = 0;
            smemf[FC_OFF + t] = 0.f;
        }
    }

    float dvg_reg[32];
    edge_chunk<0>(smemf, smemu, Wr, br, v_in, s_out, v_out, base, n_edges, dvg_reg);
    edge_chunk<1>(smemf, smemu, Wr, br, v_in, s_out, v_out, base, n_edges, dvg_reg);
    edge_chunk<2>(smemf, smemu, Wr, br, v_in, s_out, v_out, base, n_edges, dvg_reg);
}

// ---------- launch ----------
extern "C" void kernel_launch(void* const* d_in, const int* in_sizes, int n_in,
                              void* d_out, int out_size)
{
    const float* s     = (const float*)d_in[0];
    const float* v     = (const float*)d_in[1];
    const int*   edges = (const int*)d_in[2];
    const float* r_ij  = (const float*)d_in[3];
    const float* rnorm = (const float*)d_in[4];
    const float* W1    = (const float*)d_in[5];
    const float* b1    = (const float*)d_in[6];
    const float* W2    = (const float*)d_in[7];
    const float* b2    = (const float*)d_in[8];
    const float* Wr    = (const float*)d_in[9];
    const float* br    = (const float*)d_in[10];

    const int n_nodes = in_sizes[0] / EMB;
    const int n_edges = in_sizes[2] / 2;

    float* s_out = (float*)d_out;
    float* v_out = s_out + (size_t)n_nodes * EMB;

    static cudaStream_t s2 = nullptr;
    static cudaEvent_t ev_fork = nullptr, ev_join = nullptr;
    static int* hist_ptr = nullptr;
    if (!s2) {
        cudaStreamCreateWithFlags(&s2, cudaStreamNonBlocking);
        cudaEventCreateWithFlags(&ev_fork, cudaEventDisableTiming);
        cudaEventCreateWithFlags(&ev_join, cudaEventDisableTiming);
        cudaFuncSetAttribute(gemm1_kernel,
            cudaFuncAttributeMaxDynamicSharedMemorySize, TG_SMEM_BYTES);
        cudaFuncSetAttribute(gemm2_kernel,
            cudaFuncAttributeMaxDynamicSharedMemorySize, TG_SMEM_BYTES);
        cudaFuncSetAttribute(edge_kernel,
            cudaFuncAttributeMaxDynamicSharedMemorySize, EDGE_SMEM_BYTES);
        cudaGetSymbolAddress((void**)&hist_ptr, g_hist);
    }

    // fork: side stream does output-init copies + edge sort, overlapped with GEMMs
    cudaEventRecord(ev_fork, 0);
    cudaStreamWaitEvent(s2, ev_fork, 0);
    cudaMemcpyAsync(s_out, s, (size_t)n_nodes * EMB * sizeof(float),
                    cudaMemcpyDeviceToDevice, s2);
    cudaMemcpyAsync(v_out, v, (size_t)n_nodes * 3 * EMB * sizeof(float),
                    cudaMemcpyDeviceToDevice, s2);
    cudaMemsetAsync(hist_ptr, 0, N_NODES * sizeof(int), s2);
    hist_kernel<<<(n_edges + 255) / 256, 256, 0, s2>>>(edges, n_edges);
    scan_kernel<<<1, 1024, 0, s2>>>();
    scatter_kernel<<<(n_edges + 255) / 256, 256, 0, s2>>>(edges, n_edges);
    cudaEventRecord(ev_join, s2);

    const int tc_grid = (n_nodes + 127) / 128;
    gemm1_kernel<<<tc_grid, 256, TG_SMEM_BYTES>>>(s, W1, b1, n_nodes);
    gemm2_kernel<<<tc_grid, 256, TG_SMEM_BYTES>>>(W2, b2, n_nodes);

    // join: edge kernel needs sorted edges + initialized outputs + g_spass
    cudaStreamWaitEvent(0, ev_join, 0);
    edge_kernel<<<(n_edges + EPB - 1) / EPB, 256, EDGE_SMEM_BYTES>>>(
        r_ij, rnorm, Wr, br, v, s_out, v_out, n_edges);
}

// round 11
// speedup vs baseline: 1.8290x; 1.8290x over previous
#include <cuda_runtime.h>
#include <cstdint>

#define N_NODES 50000
#define MAX_EDGES 800000
#define EMB 128
#define NRBF 20

// Scratch (static device arrays are allowed; runtime alloc is not)
__device__ float g_h[(size_t)N_NODES * EMB];         // silu(s@W1+b1)
__device__ float g_spass[(size_t)N_NODES * 3 * EMB]; // h@W2+b2
__device__ int   g_hist[N_NODES];                    // histogram -> offsets (cursor)
__device__ int2  g_sorted_sd[MAX_EDGES];             // (src, dst) sorted by dst
__device__ int   g_sorted_idx[MAX_EDGES];            // original edge index

// ---------- f32x2 helpers (edge kernel) ----------
__device__ __forceinline__ unsigned long long fma2(unsigned long long a,
                                                   unsigned long long b,
                                                   unsigned long long c) {
    unsigned long long d;
    asm("fma.rn.f32x2 %0, %1, %2, %3;" : "=l"(d) : "l"(a), "l"(b), "l"(c));
    return d;
}
__device__ __forceinline__ unsigned long long packf(float lo, float hi) {
    unsigned long long r;
    asm("mov.b64 %0, {%1, %2};" : "=l"(r) : "f"(lo), "f"(hi));
    return r;
}
__device__ __forceinline__ float lof(unsigned long long v) {
    return __uint_as_float((unsigned)(v & 0xffffffffull));
}
__device__ __forceinline__ float hif(unsigned long long v) {
    return __uint_as_float((unsigned)(v >> 32));
}

// ---------- tf32 mma helpers ----------
__device__ __forceinline__ unsigned tf32_of(float f) {
    unsigned r;
    asm("cvt.rna.tf32.f32 %0, %1;" : "=r"(r) : "f"(f));
    return r;
}
__device__ __forceinline__ void mma_tf32(float c[4],
                                         unsigned a0, unsigned a1,
                                         unsigned a2, unsigned a3,
                                         unsigned b0, unsigned b1) {
    asm("mma.sync.aligned.m16n8k8.row.col.f32.tf32.tf32.f32 "
        "{%0,%1,%2,%3}, {%4,%5,%6,%7}, {%8,%9}, {%0,%1,%2,%3};"
        : "+f"(c[0]), "+f"(c[1]), "+f"(c[2]), "+f"(c[3])
        : "r"(a0), "r"(a1), "r"(a2), "r"(a3), "r"(b0), "r"(b1));
}

// ---------- tensor-core GEMM: C[M x N] = act(A[M x 128] @ W[128 x N] + b) ----------
// 256 threads / 8 warps (2m x 4n). Block tile 64(M) x 64(N) per n-pass.
// Warp tile 32(M) x 16(N). smem 43KB -> 5 blocks/SM (occupancy-first).
#define A_STRIDE 132
#define W_STRIDE 72
#define TG_SMEM_BYTES ((64 * A_STRIDE + 32 * W_STRIDE) * 4)

template <int N, int ACT>
__device__ __forceinline__ void gemm_tc_body(
    const float* __restrict__ A, const float* __restrict__ W,
    const float* __restrict__ bias, float* __restrict__ C, int M)
{
    extern __shared__ __align__(16) unsigned smem_u[];
    unsigned* A_sh = smem_u;                   // [64][A_STRIDE]
    unsigned* W_sh = smem_u + 64 * A_STRIDE;   // [32][W_STRIDE]

    const int t = threadIdx.x;
    const int w = t >> 5;
    const int lane = t & 31;
    const int mw = w & 1;        // 0..1 (m warp: rows 32*mw..+31)
    const int nw = w >> 1;       // 0..3 (n warp: cols 16*nw..+15)
    const int lr = lane >> 2;
    const int lc = lane & 3;
    const int m0 = blockIdx.x * 64;

    // stage A tile (64 x 128) with tf32 rounding
    for (int lin = t; lin < 64 * 128; lin += 256) {
        int m = lin >> 7, k = lin & 127;
        float val = (m0 + m < M) ? A[(size_t)(m0 + m) * 128 + k] : 0.f;
        A_sh[m * A_STRIDE + k] = tf32_of(val);
    }

    for (int n0 = 0; n0 < N; n0 += 64) {
        float acc[2][2][4];
        #pragma unroll
        for (int i = 0; i < 2; i++)
            #pragma unroll
            for (int j = 0; j < 2; j++)
                #pragma unroll
                for (int x = 0; x < 4; x++) acc[i][j][x] = 0.f;

        #pragma unroll 1
        for (int kc = 0; kc < 4; kc++) {
            __syncthreads();  // protect W_sh (and order A staging on first pass)
            for (int lin = t; lin < 32 * 64; lin += 256) {
                int kk = lin >> 6, nn = lin & 63;
                W_sh[kk * W_STRIDE + nn] =
                    tf32_of(W[(size_t)(kc * 32 + kk) * N + n0 + nn]);
            }
            __syncthreads();

            #pragma unroll
            for (int k8 = 0; k8 < 4; k8++) {
                const int kl = k8 * 8;
                const int kg = kc * 32 + kl;
                unsigned a[2][4];
                #pragma unroll
                for (int i = 0; i < 2; i++) {
                    const int r = mw * 32 + i * 16 + lr;
                    a[i][0] = A_sh[r * A_STRIDE + kg + lc];
                    a[i][1] = A_sh[(r + 8) * A_STRIDE + kg + lc];
                    a[i][2] = A_sh[r * A_STRIDE + kg + lc + 4];
                    a[i][3] = A_sh[(r + 8) * A_STRIDE + kg + lc + 4];
                }
                #pragma unroll
                for (int j = 0; j < 2; j++) {
                    const int n = nw * 16 + j * 8 + lr;
                    unsigned b0 = W_sh[(kl + lc) * W_STRIDE + n];
                    unsigned b1 = W_sh[(kl + lc + 4) * W_STRIDE + n];
                    mma_tf32(acc[0][j], a[0][0], a[0][1], a[0][2], a[0][3], b0, b1);
                    mma_tf32(acc[1][j], a[1][0], a[1][1], a[1][2], a[1][3], b0, b1);
                }
            }
        }

        // epilogue: bias (+silu), STG.64 pairs
        #pragma unroll
        for (int i = 0; i < 2; i++) {
            const int r1 = m0 + mw * 32 + i * 16 + lr;
            const int r2 = r1 + 8;
            #pragma unroll
            for (int j = 0; j < 2; j++) {
                const int cb = n0 + nw * 16 + j * 8 + lc * 2;
                const float b0f = bias[cb], b1f = bias[cb + 1];
                float x0 = acc[i][j][0] + b0f;
                float x1 = acc[i][j][1] + b1f;
                float x2 = acc[i][j][2] + b0f;
                float x3 = acc[i][j][3] + b1f;
                if (ACT) {
                    x0 = x0 / (1.0f + __expf(-x0));
                    x1 = x1 / (1.0f + __expf(-x1));
                    x2 = x2 / (1.0f + __expf(-x2));
                    x3 = x3 / (1.0f + __expf(-x3));
                }
                if (r1 < M) *(float2*)(C + (size_t)r1 * N + cb) = make_float2(x0, x1);
                if (r2 < M) *(float2*)(C + (size_t)r2 * N + cb) = make_float2(x2, x3);
            }
        }
    }
}

__global__ __launch_bounds__(256) void gemm1_kernel(
    const float* __restrict__ A, const float* __restrict__ W,
    const float* __restrict__ bias, int M)
{
    gemm_tc_body<128, 1>(A, W, bias, g_h, M);
}

__global__ __launch_bounds__(256) void gemm2_kernel(
    const float* __restrict__ W, const float* __restrict__ bias, int M)
{
    gemm_tc_body<384, 0>(g_h, W, bias, g_spass, M);
}

// ---------- counting sort of edges by dst ----------
__global__ __launch_bounds__(256) void hist_kernel(const int* __restrict__ edges,
                                                   int n_edges)
{
    int e = blockIdx.x * 256 + threadIdx.x;
    if (e < n_edges) atomicAdd(&g_hist[edges[2 * e + 1]], 1);
}

__global__ __launch_bounds__(1024) void scan_kernel()
{
    __shared__ int warp_sums[32];
    __shared__ int running_sh;
    const int t = threadIdx.x;
    const int lane = t & 31, wid = t >> 5;
    if (t == 0) running_sh = 0;
    __syncthreads();

    for (int base = 0; base < N_NODES; base += 1024) {
        int i = base + t;
        int v = (i < N_NODES) ? g_hist[i] : 0;
        int x = v;
        #pragma unroll
        for (int d = 1; d < 32; d <<= 1) {
            int y = __shfl_up_sync(~0u, x, d);
            if (lane >= d) x += y;
        }
        if (lane == 31) warp_sums[wid] = x;
        __syncthreads();
        if (wid == 0) {
            int s2 = warp_sums[lane];
            #pragma unroll
            for (int d = 1; d < 32; d <<= 1) {
                int y = __shfl_up_sync(~0u, s2, d);
                if (lane >= d) s2 += y;
            }
            warp_sums[lane] = s2;
        }
        __syncthreads();
        int incl = x + (wid > 0 ? warp_sums[wid - 1] : 0) + running_sh;
        if (i < N_NODES) g_hist[i] = incl - v;
        __syncthreads();
        if (t == 1023) running_sh = incl;
        __syncthreads();
    }
}

__global__ __launch_bounds__(256) void scatter_kernel(const int* __restrict__ edges,
                                                      int n_edges)
{
    int e = blockIdx.x * 256 + threadIdx.x;
    if (e < n_edges) {
        int2 sd = ((const int2*)edges)[e];
        int pos = atomicAdd(&g_hist[sd.y], 1);
        g_sorted_sd[pos] = sd;
        g_sorted_idx[pos] = e;
    }
}

// ---------- Edge kernel (v1, proven): dst-sorted, register-cached gathers ----------
__global__ __launch_bounds__(128) void edge_kernel(
    const float* __restrict__ r_ij,        // [E]
    const float* __restrict__ rnorm,       // [E][3]
    const float* __restrict__ Wr,          // [20][384]
    const float* __restrict__ br,          // [384]
    const float* __restrict__ v_in,        // [N][3][128]
    float* __restrict__ s_out,             // [N][128]
    float* __restrict__ v_out,             // [N][3][128]
    int n_edges)
{
    __shared__ __align__(16) float rb_sh[128][24];  // 20 rbf, fc, rn0..rn2
    __shared__ int src_sh[128];
    __shared__ int dst_sh[128];

    const int t = threadIdx.x;
    const int base = blockIdx.x * 128;

    unsigned long long wrP0[10], wrP1[10], wrP2[10];
    #pragma unroll
    for (int p = 0; p < 10; p++) {
        wrP0[p] = packf(Wr[(2 * p) * 384 + t],       Wr[(2 * p + 1) * 384 + t]);
        wrP1[p] = packf(Wr[(2 * p) * 384 + 128 + t], Wr[(2 * p + 1) * 384 + 128 + t]);
        wrP2[p] = packf(Wr[(2 * p) * 384 + 256 + t], Wr[(2 * p + 1) * 384 + 256 + t]);
    }
    const float br0 = br[t], br1 = br[128 + t], br2 = br[256 + t];

    const int e_my = base + t;
    if (e_my < n_edges) {
        int2 sd = g_sorted_sd[e_my];
        int idx = g_sorted_idx[e_my];
        src_sh[t] = sd.x;
        dst_sh[t] = sd.y;
        float r = r_ij[idx];
        float inv_r = 1.0f / r;
        float q = r * 0.2f;
        #pragma unroll
        for (int n = 1; n <= NRBF; n++) {
            rb_sh[t][n - 1] = sinpif((float)n * q) * inv_r;
        }
        float fc = (r <= 5.0f) ? 0.5f * (cospif(q) + 1.0f) : 0.0f;
        rb_sh[t][20] = fc;
        rb_sh[t][21] = rnorm[3 * idx + 0];
        rb_sh[t][22] = rnorm[3 * idx + 1];
        rb_sh[t][23] = rnorm[3 * idx + 2];
    }
    __syncthreads();

    const int cnt = min(128, n_edges - base);

    int dst_prev = -1;
    float sp0 = 0.f, sp1 = 0.f, sp2 = 0.f, vv0 = 0.f, vv1 = 0.f, vv2 = 0.f;

    for (int e = 0; e < cnt; e++) {
        const int src = src_sh[e];
        const int dst = dst_sh[e];

        if (dst != dst_prev) {
            const float* sp = g_spass + (size_t)dst * 384 + t;
            const float* vp = v_in + (size_t)dst * 384 + t;
            sp0 = sp[0]; sp1 = sp[128]; sp2 = sp[256];
            vv0 = vp[0]; vv1 = vp[128]; vv2 = vp[256];
            dst_prev = dst;
        }

        const float* row = rb_sh[e];
        unsigned long long a0 = 0ull, a1 = 0ull, a2 = 0ull;
        #pragma unroll
        for (int p = 0; p < 5; p++) {
            ulonglong2 rp = ((const ulonglong2*)row)[p];
            a0 = fma2(rp.x, wrP0[2 * p], a0);
            a0 = fma2(rp.y, wrP0[2 * p + 1], a0);
            a1 = fma2(rp.x, wrP1[2 * p], a1);
            a1 = fma2(rp.y, wrP1[2 * p + 1], a1);
            a2 = fma2(rp.x, wrP2[2 * p], a2);
            a2 = fma2(rp.y, wrP2[2 * p + 1], a2);
        }
        const float fc  = row[20];
        const float rn0 = row[21], rn1 = row[22], rn2 = row[23];

        float g   = (lof(a0) + hif(a0) + br0) * fc * sp0;
        float ds  = (lof(a1) + hif(a1) + br1) * fc * sp1;
        float rep = (lof(a2) + hif(a2) + br2) * fc * sp2;

        atomicAdd(s_out + (size_t)src * 128 + t, ds);

        float* vo = v_out + (size_t)src * 384 + t;
        atomicAdd(vo,       fmaf(vv0, g, rn0 * rep));
        atomicAdd(vo + 128, fmaf(vv1, g, rn1 * rep));
        atomicAdd(vo + 256, fmaf(vv2, g, rn2 * rep));
    }
}

// ---------- launch ----------
extern "C" void kernel_launch(void* const* d_in, const int* in_sizes, int n_in,
                              void* d_out, int out_size)
{
    const float* s     = (const float*)d_in[0];
    const float* v     = (const float*)d_in[1];
    const int*   edges = (const int*)d_in[2];
    const float* r_ij  = (const float*)d_in[3];
    const float* rnorm = (const float*)d_in[4];
    const float* W1    = (const float*)d_in[5];
    const float* b1    = (const float*)d_in[6];
    const float* W2    = (const float*)d_in[7];
    const float* b2    = (const float*)d_in[8];
    const float* Wr    = (const float*)d_in[9];
    const float* br    = (const float*)d_in[10];

    const int n_nodes = in_sizes[0] / EMB;
    const int n_edges = in_sizes[2] / 2;

    float* s_out = (float*)d_out;
    float* v_out = s_out + (size_t)n_nodes * EMB;

    static cudaStream_t s2 = nullptr;
    static cudaEvent_t ev_fork = nullptr, ev_join = nullptr;
    static int* hist_ptr = nullptr;
    if (!s2) {
        cudaStreamCreateWithFlags(&s2, cudaStreamNonBlocking);
        cudaEventCreateWithFlags(&ev_fork, cudaEventDisableTiming);
        cudaEventCreateWithFlags(&ev_join, cudaEventDisableTiming);
        cudaFuncSetAttribute(gemm1_kernel,
            cudaFuncAttributeMaxDynamicSharedMemorySize, TG_SMEM_BYTES);
        cudaFuncSetAttribute(gemm2_kernel,
            cudaFuncAttributeMaxDynamicSharedMemorySize, TG_SMEM_BYTES);
        cudaGetSymbolAddress((void**)&hist_ptr, g_hist);
    }

    // fork: side stream does output-init copies + edge sort, overlapped with GEMMs
    cudaEventRecord(ev_fork, 0);
    cudaStreamWaitEvent(s2, ev_fork, 0);
    cudaMemcpyAsync(s_out, s, (size_t)n_nodes * EMB * sizeof(float),
                    cudaMemcpyDeviceToDevice, s2);
    cudaMemcpyAsync(v_out, v, (size_t)n_nodes * 3 * EMB * sizeof(float),
                    cudaMemcpyDeviceToDevice, s2);
    cudaMemsetAsync(hist_ptr, 0, N_NODES * sizeof(int), s2);
    hist_kernel<<<(n_edges + 255) / 256, 256, 0, s2>>>(edges, n_edges);
    scan_kernel<<<1, 1024, 0, s2>>>();
    scatter_kernel<<<(n_edges + 255) / 256, 256, 0, s2>>>(edges, n_edges);
    cudaEventRecord(ev_join, s2);

    const int tc_grid = (n_nodes + 63) / 64;
    gemm1_kernel<<<tc_grid, 256, TG_SMEM_BYTES>>>(s, W1, b1, n_nodes);
    gemm2_kernel<<<tc_grid, 256, TG_SMEM_BYTES>>>(W2, b2, n_nodes);

    // join: edge kernel needs sorted edges + initialized outputs + g_spass
    cudaStreamWaitEvent(0, ev_join, 0);
    edge_kernel<<<(n_edges + 127) / 128, 128>>>(r_ij, rnorm, Wr, br,
                                                v, s_out, v_out, n_edges);
}

// round 12
// speedup vs baseline: 1.9948x; 1.0907x over previous
#include <cuda_runtime.h>
#include <cstdint>

#define N_NODES 50000
#define MAX_EDGES 800000
#define EMB 128
#define NRBF 20

// Scratch (static device arrays are allowed; runtime alloc is not)
__device__ float g_h[(size_t)N_NODES * EMB];         // silu(s@W1+b1)
__device__ float g_spass[(size_t)N_NODES * 3 * EMB]; // h@W2+b2
__device__ int   g_hist[N_NODES];                    // histogram -> offsets (cursor)
__device__ int2  g_sorted_sd[MAX_EDGES];             // (src, dst) sorted by dst
__device__ int   g_sorted_idx[MAX_EDGES];            // original edge index

// ---------- f32x2 helpers (edge kernel) ----------
__device__ __forceinline__ unsigned long long fma2(unsigned long long a,
                                                   unsigned long long b,
                                                   unsigned long long c) {
    unsigned long long d;
    asm("fma.rn.f32x2 %0, %1, %2, %3;" : "=l"(d) : "l"(a), "l"(b), "l"(c));
    return d;
}
__device__ __forceinline__ unsigned long long packf(float lo, float hi) {
    unsigned long long r;
    asm("mov.b64 %0, {%1, %2};" : "=l"(r) : "f"(lo), "f"(hi));
    return r;
}
__device__ __forceinline__ float lof(unsigned long long v) {
    return __uint_as_float((unsigned)(v & 0xffffffffull));
}
__device__ __forceinline__ float hif(unsigned long long v) {
    return __uint_as_float((unsigned)(v >> 32));
}

// ---------- mma / cp.async helpers ----------
__device__ __forceinline__ void mma_tf32(float c[4],
                                         unsigned a0, unsigned a1,
                                         unsigned a2, unsigned a3,
                                         unsigned b0, unsigned b1) {
    asm("mma.sync.aligned.m16n8k8.row.col.f32.tf32.tf32.f32 "
        "{%0,%1,%2,%3}, {%4,%5,%6,%7}, {%8,%9}, {%0,%1,%2,%3};"
        : "+f"(c[0]), "+f"(c[1]), "+f"(c[2]), "+f"(c[3])
        : "r"(a0), "r"(a1), "r"(a2), "r"(a3), "r"(b0), "r"(b1));
}
__device__ __forceinline__ void cp16(void* dst, const void* src) {
    unsigned d = (unsigned)__cvta_generic_to_shared(dst);
    asm volatile("cp.async.cg.shared.global [%0], [%1], 16;"
                 :: "r"(d), "l"(src));
}
__device__ __forceinline__ void cp16_pred(void* dst, const void* src, bool pred) {
    unsigned d = (unsigned)__cvta_generic_to_shared(dst);
    int sz = pred ? 16 : 0;
    asm volatile("cp.async.cg.shared.global [%0], [%1], 16, %2;"
                 :: "r"(d), "l"(src), "r"(sz));
}
#define CP_COMMIT() asm volatile("cp.async.commit_group;")
#define CP_WAIT0()  asm volatile("cp.async.wait_group 0;")

// ---------- tensor-core GEMM: C[M x 128k] = act(A[M x 128] @ W + b) ----------
// r9 shapes: 256 threads / 8 warps (4m x 2n), block tile 128M x 64N per pass,
// warp tile 32x32. W double-buffered via cp.async; raw fp32 bits fed to tf32 MMA.
#define A_STRIDE 132
#define W_STRIDE 72
#define TG_SMEM_BYTES ((128 * A_STRIDE + 2 * 32 * W_STRIDE) * 4)

template <int N, int ACT>
__device__ __forceinline__ void gemm_tc_body(
    const float* __restrict__ A, const float* __restrict__ W,
    const float* __restrict__ bias, float* __restrict__ C, int M)
{
    extern __shared__ __align__(16) unsigned smem_u[];
    unsigned* A_sh = smem_u;                  // [128][A_STRIDE]
    unsigned* W_b0 = smem_u + 128 * A_STRIDE; // [32][W_STRIDE]
    unsigned* W_b1 = W_b0 + 32 * W_STRIDE;

    const int t = threadIdx.x;
    const int w = t >> 5;
    const int lane = t & 31;
    const int mw = w & 3;
    const int nw = w >> 2;
    const int lr = lane >> 2;
    const int lc = lane & 3;
    const int m0 = blockIdx.x * 128;

    // ---- stage A tile (128 x 128) raw fp32 via cp.async
    for (int lin = t; lin < 128 * 32; lin += 256) {
        int m = lin >> 5, j = lin & 31;
        int mg = m0 + m;
        bool ok = mg < M;
        int mc = ok ? mg : (M - 1);
        cp16_pred(A_sh + m * A_STRIDE + j * 4, A + (size_t)mc * 128 + j * 4, ok);
    }

    for (int n0 = 0; n0 < N; n0 += 64) {
        __syncthreads();  // prev pass fully consumed W buffers
        // stage W chunk 0 into buf0
        for (int lin = t; lin < 32 * 16; lin += 256) {
            int kk = lin >> 4, j = lin & 15;
            cp16(W_b0 + kk * W_STRIDE + j * 4, W + (size_t)kk * N + n0 + j * 4);
        }
        CP_COMMIT();

        float acc[2][4][4];
        #pragma unroll
        for (int i = 0; i < 2; i++)
            #pragma unroll
            for (int j = 0; j < 4; j++)
                #pragma unroll
                for (int x = 0; x < 4; x++) acc[i][j][x] = 0.f;

        #pragma unroll
        for (int kc = 0; kc < 4; kc++) {
            CP_WAIT0();
            __syncthreads();  // chunk kc visible to all; prior-buffer reads done

            // prefetch chunk kc+1 into the other buffer during this chunk's MMAs
            if (kc < 3) {
                unsigned* Wnxt = ((kc + 1) & 1) ? W_b1 : W_b0;
                for (int lin = t; lin < 32 * 16; lin += 256) {
                    int kk = lin >> 4, j = lin & 15;
                    cp16(Wnxt + kk * W_STRIDE + j * 4,
                         W + (size_t)((kc + 1) * 32 + kk) * N + n0 + j * 4);
                }
                CP_COMMIT();
            }

            unsigned* Wcur = (kc & 1) ? W_b1 : W_b0;
            #pragma unroll
            for (int k8 = 0; k8 < 4; k8++) {
                const int kl = k8 * 8;
                const int kg = kc * 32 + kl;
                unsigned a[2][4];
                #pragma unroll
                for (int i = 0; i < 2; i++) {
                    const int r = mw * 32 + i * 16 + lr;
                    a[i][0] = A_sh[r * A_STRIDE + kg + lc];
                    a[i][1] = A_sh[(r + 8) * A_STRIDE + kg + lc];
                    a[i][2] = A_sh[r * A_STRIDE + kg + lc + 4];
                    a[i][3] = A_sh[(r + 8) * A_STRIDE + kg + lc + 4];
                }
                #pragma unroll
                for (int j = 0; j < 4; j++) {
                    const int n = nw * 32 + j * 8 + lr;
                    unsigned b0 = Wcur[(kl + lc) * W_STRIDE + n];
                    unsigned b1 = Wcur[(kl + lc + 4) * W_STRIDE + n];
                    mma_tf32(acc[0][j], a[0][0], a[0][1], a[0][2], a[0][3], b0, b1);
                    mma_tf32(acc[1][j], a[1][0], a[1][1], a[1][2], a[1][3], b0, b1);
                }
            }
        }

        // epilogue: bias (+silu), STG.64 pairs
        #pragma unroll
        for (int i = 0; i < 2; i++) {
            const int r1 = m0 + mw * 32 + i * 16 + lr;
            const int r2 = r1 + 8;
            #pragma unroll
            for (int j = 0; j < 4; j++) {
                const int cb = n0 + nw * 32 + j * 8 + lc * 2;
                const float b0f = bias[cb], b1f = bias[cb + 1];
                float x0 = acc[i][j][0] + b0f;
                float x1 = acc[i][j][1] + b1f;
                float x2 = acc[i][j][2] + b0f;
                float x3 = acc[i][j][3] + b1f;
                if (ACT) {
                    x0 = x0 / (1.0f + __expf(-x0));
                    x1 = x1 / (1.0f + __expf(-x1));
                    x2 = x2 / (1.0f + __expf(-x2));
                    x3 = x3 / (1.0f + __expf(-x3));
                }
                if (r1 < M) *(float2*)(C + (size_t)r1 * N + cb) = make_float2(x0, x1);
                if (r2 < M) *(float2*)(C + (size_t)r2 * N + cb) = make_float2(x2, x3);
            }
        }
    }
}

__global__ __launch_bounds__(256) void gemm1_kernel(
    const float* __restrict__ A, const float* __restrict__ W,
    const float* __restrict__ bias, int M)
{
    gemm_tc_body<128, 1>(A, W, bias, g_h, M);
}

__global__ __launch_bounds__(256) void gemm2_kernel(
    const float* __restrict__ W, const float* __restrict__ bias, int M)
{
    gemm_tc_body<384, 0>(g_h, W, bias, g_spass, M);
}

// ---------- counting sort of edges by dst ----------
__global__ __launch_bounds__(256) void hist_kernel(const int* __restrict__ edges,
                                                   int n_edges)
{
    int e = blockIdx.x * 256 + threadIdx.x;
    if (e < n_edges) atomicAdd(&g_hist[edges[2 * e + 1]], 1);
}

__global__ __launch_bounds__(1024) void scan_kernel()
{
    __shared__ int warp_sums[32];
    __shared__ int running_sh;
    const int t = threadIdx.x;
    const int lane = t & 31, wid = t >> 5;
    if (t == 0) running_sh = 0;
    __syncthreads();

    for (int base = 0; base < N_NODES; base += 1024) {
        int i = base + t;
        int v = (i < N_NODES) ? g_hist[i] : 0;
        int x = v;
        #pragma unroll
        for (int d = 1; d < 32; d <<= 1) {
            int y = __shfl_up_sync(~0u, x, d);
            if (lane >= d) x += y;
        }
        if (lane == 31) warp_sums[wid] = x;
        __syncthreads();
        if (wid == 0) {
            int s2 = warp_sums[lane];
            #pragma unroll
            for (int d = 1; d < 32; d <<= 1) {
                int y = __shfl_up_sync(~0u, s2, d);
                if (lane >= d) s2 += y;
            }
            warp_sums[lane] = s2;
        }
        __syncthreads();
        int incl = x + (wid > 0 ? warp_sums[wid - 1] : 0) + running_sh;
        if (i < N_NODES) g_hist[i] = incl - v;
        __syncthreads();
        if (t == 1023) running_sh = incl;
        __syncthreads();
    }
}

__global__ __launch_bounds__(256) void scatter_kernel(const int* __restrict__ edges,
                                                      int n_edges)
{
    int e = blockIdx.x * 256 + threadIdx.x;
    if (e < n_edges) {
        int2 sd = ((const int2*)edges)[e];
        int pos = atomicAdd(&g_hist[sd.y], 1);
        g_sorted_sd[pos] = sd;
        g_sorted_idx[pos] = e;
    }
}

// ---------- Edge kernel (v1, proven): dst-sorted, register-cached gathers ----------
__global__ __launch_bounds__(128) void edge_kernel(
    const float* __restrict__ r_ij,        // [E]
    const float* __restrict__ rnorm,       // [E][3]
    const float* __restrict__ Wr,          // [20][384]
    const float* __restrict__ br,          // [384]
    const float* __restrict__ v_in,        // [N][3][128]
    float* __restrict__ s_out,             // [N][128]
    float* __restrict__ v_out,             // [N][3][128]
    int n_edges)
{
    __shared__ __align__(16) float rb_sh[128][24];  // 20 rbf, fc, rn0..rn2
    __shared__ int src_sh[128];
    __shared__ int dst_sh[128];

    const int t = threadIdx.x;
    const int base = blockIdx.x * 128;

    unsigned long long wrP0[10], wrP1[10], wrP2[10];
    #pragma unroll
    for (int p = 0; p < 10; p++) {
        wrP0[p] = packf(Wr[(2 * p) * 384 + t],       Wr[(2 * p + 1) * 384 + t]);
        wrP1[p] = packf(Wr[(2 * p) * 384 + 128 + t], Wr[(2 * p + 1) * 384 + 128 + t]);
        wrP2[p] = packf(Wr[(2 * p) * 384 + 256 + t], Wr[(2 * p + 1) * 384 + 256 + t]);
    }
    const float br0 = br[t], br1 = br[128 + t], br2 = br[256 + t];

    const int e_my = base + t;
    if (e_my < n_edges) {
        int2 sd = g_sorted_sd[e_my];
        int idx = g_sorted_idx[e_my];
        src_sh[t] = sd.x;
        dst_sh[t] = sd.y;
        float r = r_ij[idx];
        float inv_r = 1.0f / r;
        float q = r * 0.2f;
        #pragma unroll
        for (int n = 1; n <= NRBF; n++) {
            rb_sh[t][n - 1] = sinpif((float)n * q) * inv_r;
        }
        float fc = (r <= 5.0f) ? 0.5f * (cospif(q) + 1.0f) : 0.0f;
        rb_sh[t][20] = fc;
        rb_sh[t][21] = rnorm[3 * idx + 0];
        rb_sh[t][22] = rnorm[3 * idx + 1];
        rb_sh[t][23] = rnorm[3 * idx + 2];
    }
    __syncthreads();

    const int cnt = min(128, n_edges - base);

    int dst_prev = -1;
    float sp0 = 0.f, sp1 = 0.f, sp2 = 0.f, vv0 = 0.f, vv1 = 0.f, vv2 = 0.f;

    for (int e = 0; e < cnt; e++) {
        const int src = src_sh[e];
        const int dst = dst_sh[e];

        if (dst != dst_prev) {
            const float* sp = g_spass + (size_t)dst * 384 + t;
            const float* vp = v_in + (size_t)dst * 384 + t;
            sp0 = sp[0]; sp1 = sp[128]; sp2 = sp[256];
            vv0 = vp[0]; vv1 = vp[128]; vv2 = vp[256];
            dst_prev = dst;
        }

        const float* row = rb_sh[e];
        unsigned long long a0 = 0ull, a1 = 0ull, a2 = 0ull;
        #pragma unroll
        for (int p = 0; p < 5; p++) {
            ulonglong2 rp = ((const ulonglong2*)row)[p];
            a0 = fma2(rp.x, wrP0[2 * p], a0);
            a0 = fma2(rp.y, wrP0[2 * p + 1], a0);
            a1 = fma2(rp.x, wrP1[2 * p], a1);
            a1 = fma2(rp.y, wrP1[2 * p + 1], a1);
            a2 = fma2(rp.x, wrP2[2 * p], a2);
            a2 = fma2(rp.y, wrP2[2 * p + 1], a2);
        }
        const float fc  = row[20];
        const float rn0 = row[21], rn1 = row[22], rn2 = row[23];

        float g   = (lof(a0) + hif(a0) + br0) * fc * sp0;
        float ds  = (lof(a1) + hif(a1) + br1) * fc * sp1;
        float rep = (lof(a2) + hif(a2) + br2) * fc * sp2;

        atomicAdd(s_out + (size_t)src * 128 + t, ds);

        float* vo = v_out + (size_t)src * 384 + t;
        atomicAdd(vo,       fmaf(vv0, g, rn0 * rep));
        atomicAdd(vo + 128, fmaf(vv1, g, rn1 * rep));
        atomicAdd(vo + 256, fmaf(vv2, g, rn2 * rep));
    }
}

// ---------- launch ----------
extern "C" void kernel_launch(void* const* d_in, const int* in_sizes, int n_in,
                              void* d_out, int out_size)
{
    const float* s     = (const float*)d_in[0];
    const float* v     = (const float*)d_in[1];
    const int*   edges = (const int*)d_in[2];
    const float* r_ij  = (const float*)d_in[3];
    const float* rnorm = (const float*)d_in[4];
    const float* W1    = (const float*)d_in[5];
    const float* b1    = (const float*)d_in[6];
    const float* W2    = (const float*)d_in[7];
    const float* b2    = (const float*)d_in[8];
    const float* Wr    = (const float*)d_in[9];
    const float* br    = (const float*)d_in[10];

    const int n_nodes = in_sizes[0] / EMB;
    const int n_edges = in_sizes[2] / 2;

    float* s_out = (float*)d_out;
    float* v_out = s_out + (size_t)n_nodes * EMB;

    static cudaStream_t s2 = nullptr;
    static cudaEvent_t ev_fork = nullptr, ev_join = nullptr;
    static int* hist_ptr = nullptr;
    if (!s2) {
        cudaStreamCreateWithFlags(&s2, cudaStreamNonBlocking);
        cudaEventCreateWithFlags(&ev_fork, cudaEventDisableTiming);
        cudaEventCreateWithFlags(&ev_join, cudaEventDisableTiming);
        cudaFuncSetAttribute(gemm1_kernel,
            cudaFuncAttributeMaxDynamicSharedMemorySize, TG_SMEM_BYTES);
        cudaFuncSetAttribute(gemm2_kernel,
            cudaFuncAttributeMaxDynamicSharedMemorySize, TG_SMEM_BYTES);
        cudaGetSymbolAddress((void**)&hist_ptr, g_hist);
    }

    // fork: side stream does output-init copies + edge sort, overlapped with GEMMs
    cudaEventRecord(ev_fork, 0);
    cudaStreamWaitEvent(s2, ev_fork, 0);
    cudaMemcpyAsync(s_out, s, (size_t)n_nodes * EMB * sizeof(float),
                    cudaMemcpyDeviceToDevice, s2);
    cudaMemcpyAsync(v_out, v, (size_t)n_nodes * 3 * EMB * sizeof(float),
                    cudaMemcpyDeviceToDevice, s2);
    cudaMemsetAsync(hist_ptr, 0, N_NODES * sizeof(int), s2);
    hist_kernel<<<(n_edges + 255) / 256, 256, 0, s2>>>(edges, n_edges);
    scan_kernel<<<1, 1024, 0, s2>>>();
    scatter_kernel<<<(n_edges + 255) / 256, 256, 0, s2>>>(edges, n_edges);
    cudaEventRecord(ev_join, s2);

    const int tc_grid = (n_nodes + 127) / 128;
    gemm1_kernel<<<tc_grid, 256, TG_SMEM_BYTES>>>(s, W1, b1, n_nodes);
    gemm2_kernel<<<tc_grid, 256, TG_SMEM_BYTES>>>(W2, b2, n_nodes);

    // join: edge kernel needs sorted edges + initialized outputs + g_spass
    cudaStreamWaitEvent(0, ev_join, 0);
    edge_kernel<<<(n_edges + 127) / 128, 128>>>(r_ij, rnorm, Wr, br,
                                                v, s_out, v_out, n_edges);
}